// round 16
// baseline (speedup 1.0000x reference)
#include <cuda_runtime.h>
#include <cstdint>

// ============================================================================
// WaveletKAN: out[128,4096] = x @ W^T + wavelet(x) + bias
// ONE fat kernel, grid 288, 128 thr, 72KB smem, 2 CTAs/SM => single wave.
// PLACEMENT: bids {0..15} u {148..163} are wavelet CTAs (16 SMs x 2);
// all 256 GEMM CTAs get wavelet-free SMs (bid -> LUT[bid % 148]).
//   wavelet : 32 logical CTAs x 4 images (DWT4 + register bitonic prune +
//             IDWT), write out[b,:] = wav + bias, release g_wavdone.
//   GEMM    : tf32 mma.sync, BM128 x BN64 x BK32, split-K=4, 4 warps of
//             64x32 warptiles (0.183 B LDSM/MAC), NO cvt (raw fp32 ->
//             HMMA.tf32, implicit RZ), 3-stage cp.async. After mainloop:
//             spin on g_wavdone, red.global.add.v2.f32 into out.
// Counters self-reset each replay via a 256-count gate.
// ============================================================================

#define KDIM   4096
#define SK     4
#define KSLICE (KDIM / SK)        // 1024
#define BK     32
#define NT2    (KSLICE / BK)      // 32
#define STAGES 3
#define WAV_CTAS 32
#define GEMM_CTAS 256

__device__ unsigned g_wavdone;    // wavelet completion count (self-reset)
__device__ unsigned g_gate;       // GEMM epilogue pass count (self-reset)

// ---------------------------------------------------------------------------
// GEMM helpers
// ---------------------------------------------------------------------------
__device__ __forceinline__ void cp_async16(uint32_t dst, const void* src) {
    asm volatile("cp.async.cg.shared.global [%0], [%1], 16;\n" :: "r"(dst), "l"(src));
}
__device__ __forceinline__ void ldsm_x4(uint32_t* d, uint32_t addr) {
    asm volatile("ldmatrix.sync.aligned.m8n8.x4.shared.b16 {%0,%1,%2,%3}, [%4];"
        : "=r"(d[0]), "=r"(d[1]), "=r"(d[2]), "=r"(d[3]) : "r"(addr));
}
__device__ __forceinline__ void mma_tf32(float* c, const uint32_t* a,
                                         uint32_t b0, uint32_t b1) {
    asm("mma.sync.aligned.m16n8k8.row.col.f32.tf32.tf32.f32 "
        "{%0,%1,%2,%3}, {%4,%5,%6,%7}, {%8,%9}, {%0,%1,%2,%3};"
        : "+f"(c[0]), "+f"(c[1]), "+f"(c[2]), "+f"(c[3])
        : "r"(a[0]), "r"(a[1]), "r"(a[2]), "r"(a[3]), "r"(b0), "r"(b1));
}
__device__ __forceinline__ void red_add_v2(float* p, float a, float b) {
    asm volatile("red.global.add.v2.f32 [%0], {%1, %2};"
        :: "l"(p), "f"(a), "f"(b) : "memory");
}

// ---------------------------------------------------------------------------
// Per-thread register bitonic sort (ascending). Compile-time indices.
// ---------------------------------------------------------------------------
template<int N>
__device__ __forceinline__ void sortN(float* v) {
#pragma unroll
    for (int k = 2; k <= N; k <<= 1) {
#pragma unroll
        for (int j = k >> 1; j > 0; j >>= 1) {
#pragma unroll
            for (int i = 0; i < N; ++i) {
                int l = i ^ j;
                if (l > i) {
                    float a = v[i], b = v[l];
                    float mn = fminf(a, b), mx = fmaxf(a, b);
                    if ((i & k) == 0) { v[i] = mn; v[l] = mx; }
                    else              { v[i] = mx; v[l] = mn; }
                }
            }
        }
    }
}

template<int N>
__device__ __forceinline__ void prune_row(float* __restrict__ row) {
    float a[N];
#pragma unroll
    for (int i = 0; i < N; ++i) a[i] = fabsf(row[i]);
    sortN<N>(a);
    constexpr float pos = 0.4f * (float)(N - 1);
    constexpr int lo = (int)pos;
    const float frac = pos - (float)lo;
    float thr = a[lo] + frac * (a[lo + 1] - a[lo]);
#pragma unroll
    for (int i = 0; i < N; ++i) {
        float val = row[i];
        row[i] = (fabsf(val) > thr) ? val : 0.0f;
    }
}

// ---------------------------------------------------------------------------
// DWT / IDWT levels (band pitch HH+1, bands contiguous)
// ---------------------------------------------------------------------------
template<int LV>
__device__ __forceinline__ void dwt_level(const float* __restrict__ cur,
                                          float* __restrict__ nxt,
                                          float* __restrict__ Lb,
                                          const float* __restrict__ sf, int tid)
{
    constexpr int H = 64 >> LV, HH = H >> 1, P = HH + 1, BS = HH * P;
    const float s0 = sf[LV * 4 + 0], s1 = sf[LV * 4 + 1];
    const float s2 = sf[LV * 4 + 2], s3 = sf[LV * 4 + 3];
    for (int idx = tid; idx < HH * HH; idx += 128) {
        int i = idx / HH, j = idx - i * HH;
        const float* r0 = cur + (2 * i)     * H + 2 * j;
        const float* r1 = cur + (2 * i + 1) * H + 2 * j;
        float a = r0[0], b = r0[1], c = r1[0], d = r1[1];
        float ca = (a + b + c + d) * 0.5f;
        float ch = (a - b + c - d) * 0.5f;
        float cv = (a + b - c - d) * 0.5f;
        float cd = (a - b - c + d) * 0.5f;
        nxt[idx] = ca;
        Lb[0 * BS + i * P + j] = ch * s1;
        Lb[1 * BS + i * P + j] = cv * s2;
        Lb[2 * BS + i * P + j] = cd * s3;
        if (LV == 3) Lb[3 * BS + i * P + j] = ca * s0;
    }
}

template<int HH>
__device__ __forceinline__ void idwt_level(const float* __restrict__ cur,
                                           const float* __restrict__ Lb,
                                           float* __restrict__ outb, int tid)
{
    constexpr int P = HH + 1, BS = HH * P, H2 = 2 * HH;
    for (int idx = tid; idx < HH * HH; idx += 128) {
        int i = idx / HH, j = idx - i * HH;
        float ca = cur[idx];
        float ch = Lb[0 * BS + i * P + j];
        float cv = Lb[1 * BS + i * P + j];
        float cd = Lb[2 * BS + i * P + j];
        float a  = (ca + ch + cv + cd) * 0.5f;
        float b  = (ca - ch + cv - cd) * 0.5f;
        float c  = (ca + ch - cv - cd) * 0.5f;
        float d  = (ca - ch - cv + cd) * 0.5f;
        outb[(2 * i)     * H2 + 2 * j]     = a;
        outb[(2 * i)     * H2 + 2 * j + 1] = b;
        outb[(2 * i + 1) * H2 + 2 * j]     = c;
        outb[(2 * i + 1) * H2 + 2 * j + 1] = d;
    }
}

// ---------------------------------------------------------------------------
// Fat kernel
// ---------------------------------------------------------------------------
__global__ void __launch_bounds__(128, 2) fat_kernel(
    const float* __restrict__ X, const float* __restrict__ Wt,
    const float* __restrict__ bias, const float* __restrict__ sf,
    float* __restrict__ out)
{
    extern __shared__ float smem[];
    const int bid = blockIdx.x;
    const int tid = threadIdx.x;
    const int lane = tid & 31, warp = tid >> 5;

    // Placement-aware role split: bids {0..15} u {148..163} are wavelet CTAs
    const bool isWav = (bid < 16) || (bid >= 148 && bid < 164);

    if (isWav) {
        // ================= WAVELET branch: 4 images =================
        const int wavIdx = (bid < 16) ? bid : (16 + (bid - 148));   // 0..31

        float* A   = smem;          // 4096
        float* Wb0 = smem + 4096;   // 1024
        float* Wb1 = smem + 5120;   // 1024
        float* L0  = smem + 6144;   // 3*32*33 = 3168
        float* L1  = smem + 9312;   // 3*16*17 = 816
        float* L2  = smem + 10128;  // 3*8*9   = 216
        float* L3  = smem + 10344;  // 4*4*5   = 80

        for (int im = 0; im < 4; ++im) {
            const int b = wavIdx * 4 + im;
            const float4* xb = reinterpret_cast<const float4*>(X + (size_t)b * 4096);
            float4* Af = reinterpret_cast<float4*>(A);
            for (int i = tid; i < 1024; i += 128) Af[i] = xb[i];
            __syncthreads();

            dwt_level<0>(A,   Wb0, L0, sf, tid); __syncthreads();
            if (tid < 96) prune_row<32>(L0 + tid * 33);
            __syncthreads();
            dwt_level<1>(Wb0, Wb1, L1, sf, tid); __syncthreads();
            if (tid < 48) prune_row<16>(L1 + tid * 17);
            __syncthreads();
            dwt_level<2>(Wb1, Wb0, L2, sf, tid); __syncthreads();
            if (tid < 24) prune_row<8>(L2 + tid * 9);
            __syncthreads();
            dwt_level<3>(Wb0, Wb1, L3, sf, tid); __syncthreads();
            if (tid < 16) prune_row<4>(L3 + tid * 5);
            __syncthreads();

            if (tid < 16) {
                int i = tid >> 2, j = tid & 3;
                Wb0[tid] = L3[3 * 20 + i * 5 + j];
            }
            __syncthreads();
            idwt_level<4>(Wb0, L3, Wb1, tid);  __syncthreads();
            idwt_level<8>(Wb1, L2, Wb0, tid);  __syncthreads();
            idwt_level<16>(Wb0, L1, Wb1, tid); __syncthreads();
            idwt_level<32>(Wb1, L0, A, tid);   __syncthreads();

            // out[b,:] = wavelet + bias  (GEMM CTAs RED.ADD on top)
            const float4* Af4 = reinterpret_cast<const float4*>(A);
            const float4* Bv  = reinterpret_cast<const float4*>(bias);
            float4* O = reinterpret_cast<float4*>(out + (size_t)b * 4096);
            for (int i = tid; i < 1024; i += 128) {
                float4 wv = Af4[i], bb = Bv[i];
                float4 o;
                o.x = wv.x + bb.x; o.y = wv.y + bb.y;
                o.z = wv.z + bb.z; o.w = wv.w + bb.w;
                O[i] = o;
            }
            __syncthreads();
        }
        __threadfence();
        __syncthreads();
        if (tid == 0) atomicAdd(&g_wavdone, 1u);
        return;
    }

    // ================= GEMM branch: BM128 x BN64 x BK32, SK4 =================
    // enumerate GEMM index g in 0..255 over non-wavelet bids
    const int g  = (bid < 148) ? (bid - 16) : (132 + (bid - 164));
    const int kz = g & 3;                 // split-K rank (0..3)
    const int nb = g >> 2;                // N-tile (0..63); M fully covered

    const int wm = warp >> 1, wn = warp & 1;   // 2x2 warps, 64x32 warptiles

    const float* Ag = X  + (size_t)kz * KSLICE;
    const float* Bg = Wt + (size_t)nb * 64 * KDIM + (size_t)kz * KSLICE;

    const uint32_t sBase = (uint32_t)__cvta_generic_to_shared(smem);
    const uint32_t bOfs  = STAGES * 16384u;    // B region at 48 KB (8 KB stages)

    float acc[4][4][4];                        // m16-tile x n8-tile x frag
#pragma unroll
    for (int a1 = 0; a1 < 4; ++a1)
#pragma unroll
        for (int a2 = 0; a2 < 4; ++a2)
#pragma unroll
            for (int a3 = 0; a3 < 4; ++a3) acc[a1][a2][a3] = 0.0f;

    const int j = lane >> 3, r = lane & 7;
    const int cja = (j >> 1);              // A k-half select
    const int cjb = (j & 1);               // B k-half select
    uint32_t aRowB[4];
#pragma unroll
    for (int t = 0; t < 4; ++t)
        aRowB[t] = (uint32_t)((wm * 64 + t * 16 + (j & 1) * 8 + r) * 128);
    const uint32_t bRow0 = (uint32_t)((wn * 32 + (j >> 1) * 8 + r) * 128);
    const uint32_t bRow1 = bRow0 + 16u * 128u;

    // cp.async: A 128 rows x 128B (1024 chunks -> 8/thread),
    //           B  64 rows x 128B ( 512 chunks -> 4/thread). XOR-8 swizzle.
#define ISSUE(kt) {                                                            \
        int stg_ = (kt) % STAGES;                                              \
        uint32_t sa_ = sBase + (uint32_t)stg_ * 16384u;                        \
        uint32_t sb_ = sBase + bOfs + (uint32_t)stg_ * 8192u;                  \
        const float* pa_ = Ag + (size_t)(kt) * BK;                             \
        const float* pb_ = Bg + (size_t)(kt) * BK;                             \
        _Pragma("unroll")                                                      \
        for (int i_ = 0; i_ < 8; ++i_) {                                       \
            int id_ = tid + 128 * i_;                                          \
            int row_ = id_ >> 3, c_ = id_ & 7;                                 \
            uint32_t off_ = (uint32_t)(row_ * 128 + ((c_ ^ (row_ & 7)) << 4)); \
            cp_async16(sa_ + off_, pa_ + (size_t)row_ * KDIM + c_ * 4);        \
        }                                                                      \
        _Pragma("unroll")                                                      \
        for (int i_ = 0; i_ < 4; ++i_) {                                       \
            int id_ = tid + 128 * i_;                                          \
            int row_ = id_ >> 3, c_ = id_ & 7;                                 \
            uint32_t off_ = (uint32_t)(row_ * 128 + ((c_ ^ (row_ & 7)) << 4)); \
            cp_async16(sb_ + off_, pb_ + (size_t)row_ * KDIM + c_ * 4);        \
        } }

// no cvt: raw fp32 fragments feed HMMA.tf32 (HW truncates to 19 MSBs)
#define COMPUTE(stg) {                                                         \
        uint32_t aB = sBase + (uint32_t)(stg) * 16384u;                        \
        uint32_t bB = sBase + bOfs + (uint32_t)(stg) * 8192u;                  \
        _Pragma("unroll")                                                      \
        for (int s = 0; s < 4; ++s) {                                          \
            uint32_t av[4][4], bv[2][4];                                       \
            uint32_t ca = (uint32_t)((((2 * s + cja) ^ r)) << 4);              \
            uint32_t cb = (uint32_t)((((2 * s + cjb) ^ r)) << 4);              \
            ldsm_x4(bv[0], bB + bRow0 + cb);                                   \
            ldsm_x4(bv[1], bB + bRow1 + cb);                                   \
            _Pragma("unroll")                                                  \
            for (int t = 0; t < 4; ++t) ldsm_x4(av[t], aB + aRowB[t] + ca);    \
            _Pragma("unroll")                                                  \
            for (int t = 0; t < 4; ++t) {                                      \
                mma_tf32(acc[t][0], av[t], bv[0][0], bv[0][1]);                \
                mma_tf32(acc[t][1], av[t], bv[0][2], bv[0][3]);                \
                mma_tf32(acc[t][2], av[t], bv[1][0], bv[1][1]);                \
                mma_tf32(acc[t][3], av[t], bv[1][2], bv[1][3]);                \
            }                                                                  \
        } }

    ISSUE(0); asm volatile("cp.async.commit_group;");
    ISSUE(1); asm volatile("cp.async.commit_group;");

    for (int kt = 0; kt < NT2; ++kt) {
        asm volatile("cp.async.wait_group 1;");
        __syncthreads();
        COMPUTE(kt % STAGES);
        if (kt + 2 < NT2) { ISSUE(kt + 2); }
        asm volatile("cp.async.commit_group;");
    }

    // ---- wait for wavelet CTAs (they wrote out = wav + bias) ----
    if (tid == 0) {
        unsigned v;
        do {
            asm volatile("ld.acquire.gpu.global.u32 %0, [%1];"
                         : "=r"(v) : "l"(&g_wavdone));
        } while (v < WAV_CTAS);
        unsigned old = atomicAdd(&g_gate, 1u);
        if (old == GEMM_CTAS - 1) {           // last GEMM CTA resets counters
            atomicExch(&g_wavdone, 0u);
            atomicExch(&g_gate, 0u);
        }
    }
    __syncthreads();

    // ---- accumulate into out via RED.ADD.v2 ----
    const int rbase = wm * 64 + (lane >> 2);
    const int cbase = nb * 64 + wn * 32 + (lane & 3) * 2;
#pragma unroll
    for (int t = 0; t < 4; ++t) {
        int gm0 = rbase + t * 16;
#pragma unroll
        for (int nt = 0; nt < 4; ++nt) {
            int gn = cbase + nt * 8;
            red_add_v2(out + (size_t)gm0 * 4096 + gn,
                       acc[t][nt][0], acc[t][nt][1]);
            red_add_v2(out + (size_t)(gm0 + 8) * 4096 + gn,
                       acc[t][nt][2], acc[t][nt][3]);
        }
    }
#undef ISSUE
#undef COMPUTE
}

// ---------------------------------------------------------------------------
// Launch
// ---------------------------------------------------------------------------
extern "C" void kernel_launch(void* const* d_in, const int* in_sizes, int n_in,
                              void* d_out, int out_size)
{
    const float* x    = (const float*)d_in[0];   // [128, 4096]
    const float* Wt   = (const float*)d_in[1];   // [4096, 4096]
    const float* bias = (const float*)d_in[2];   // [4096]
    const float* sf   = (const float*)d_in[3];   // [4, 4]
    float* out = (float*)d_out;                  // [128, 4096]

    (void)in_sizes; (void)n_in; (void)out_size;

    const int smemBytes = STAGES * (16384 + 8192);   // 72 KB -> 2 CTAs/SM
    cudaFuncSetAttribute(fat_kernel,
                         cudaFuncAttributeMaxDynamicSharedMemorySize, smemBytes);

    fat_kernel<<<288, 128, smemBytes>>>(x, Wt, bias, sf, out);
}

// round 17
// speedup vs baseline: 1.0651x; 1.0651x over previous
#include <cuda_runtime.h>
#include <cstdint>

// ============================================================================
// WaveletKAN: out[128,4096] = x @ W^T + wavelet(x) + bias
// ONE fat kernel, grid 288, 128 thr, 96KB smem, 2 CTAs/SM => single wave.
// PLACEMENT: bids {0..15} u {148..163} are wavelet CTAs (16 SMs x 2);
// all 256 GEMM CTAs get wavelet-free SMs (bid -> LUT[bid % 148]).
//   wavelet : 32 logical CTAs x 4 images (DWT4 + register bitonic prune +
//             IDWT), write out[b,:] = wav + bias, release g_wavdone.
//   GEMM    : tf32 mma.sync, BM64 BN64 BK64, split-K=2, 3-stage cp.async,
//             NO cvt (raw fp32 -> HMMA.tf32, implicit RZ).
//             R17: software-pipelined fragment double-buffering — step s+1's
//             4 LDSMs issue before step s's 8 MMAs, exposing LDSM latency
//             once per k-tile instead of 8x.
//             After mainloop: spin on g_wavdone, red.global.add.v2.f32 into out.
// Counters self-reset each replay via a 256-count gate.
// ============================================================================

#define KDIM   4096
#define SK     2
#define KHALF  (KDIM / SK)        // 2048
#define BK     64
#define NT2    (KHALF / BK)       // 32
#define STAGES 3
#define WAV_CTAS 32
#define GEMM_CTAS 256

__device__ unsigned g_wavdone;    // wavelet completion count (self-reset)
__device__ unsigned g_gate;       // GEMM epilogue pass count (self-reset)

// ---------------------------------------------------------------------------
// GEMM helpers
// ---------------------------------------------------------------------------
__device__ __forceinline__ void cp_async16(uint32_t dst, const void* src) {
    asm volatile("cp.async.cg.shared.global [%0], [%1], 16;\n" :: "r"(dst), "l"(src));
}
__device__ __forceinline__ void ldsm_x4(uint32_t* d, uint32_t addr) {
    asm volatile("ldmatrix.sync.aligned.m8n8.x4.shared.b16 {%0,%1,%2,%3}, [%4];"
        : "=r"(d[0]), "=r"(d[1]), "=r"(d[2]), "=r"(d[3]) : "r"(addr));
}
__device__ __forceinline__ void mma_tf32(float* c, const uint32_t* a,
                                         uint32_t b0, uint32_t b1) {
    asm("mma.sync.aligned.m16n8k8.row.col.f32.tf32.tf32.f32 "
        "{%0,%1,%2,%3}, {%4,%5,%6,%7}, {%8,%9}, {%0,%1,%2,%3};"
        : "+f"(c[0]), "+f"(c[1]), "+f"(c[2]), "+f"(c[3])
        : "r"(a[0]), "r"(a[1]), "r"(a[2]), "r"(a[3]), "r"(b0), "r"(b1));
}
__device__ __forceinline__ void red_add_v2(float* p, float a, float b) {
    asm volatile("red.global.add.v2.f32 [%0], {%1, %2};"
        :: "l"(p), "f"(a), "f"(b) : "memory");
}

// ---------------------------------------------------------------------------
// Per-thread register bitonic sort (ascending). Compile-time indices.
// ---------------------------------------------------------------------------
template<int N>
__device__ __forceinline__ void sortN(float* v) {
#pragma unroll
    for (int k = 2; k <= N; k <<= 1) {
#pragma unroll
        for (int j = k >> 1; j > 0; j >>= 1) {
#pragma unroll
            for (int i = 0; i < N; ++i) {
                int l = i ^ j;
                if (l > i) {
                    float a = v[i], b = v[l];
                    float mn = fminf(a, b), mx = fmaxf(a, b);
                    if ((i & k) == 0) { v[i] = mn; v[l] = mx; }
                    else              { v[i] = mx; v[l] = mn; }
                }
            }
        }
    }
}

template<int N>
__device__ __forceinline__ void prune_row(float* __restrict__ row) {
    float a[N];
#pragma unroll
    for (int i = 0; i < N; ++i) a[i] = fabsf(row[i]);
    sortN<N>(a);
    constexpr float pos = 0.4f * (float)(N - 1);
    constexpr int lo = (int)pos;
    const float frac = pos - (float)lo;
    float thr = a[lo] + frac * (a[lo + 1] - a[lo]);
#pragma unroll
    for (int i = 0; i < N; ++i) {
        float val = row[i];
        row[i] = (fabsf(val) > thr) ? val : 0.0f;
    }
}

// ---------------------------------------------------------------------------
// DWT / IDWT levels (band pitch HH+1, bands contiguous)
// ---------------------------------------------------------------------------
template<int LV>
__device__ __forceinline__ void dwt_level(const float* __restrict__ cur,
                                          float* __restrict__ nxt,
                                          float* __restrict__ Lb,
                                          const float* __restrict__ sf, int tid)
{
    constexpr int H = 64 >> LV, HH = H >> 1, P = HH + 1, BS = HH * P;
    const float s0 = sf[LV * 4 + 0], s1 = sf[LV * 4 + 1];
    const float s2 = sf[LV * 4 + 2], s3 = sf[LV * 4 + 3];
    for (int idx = tid; idx < HH * HH; idx += 128) {
        int i = idx / HH, j = idx - i * HH;
        const float* r0 = cur + (2 * i)     * H + 2 * j;
        const float* r1 = cur + (2 * i + 1) * H + 2 * j;
        float a = r0[0], b = r0[1], c = r1[0], d = r1[1];
        float ca = (a + b + c + d) * 0.5f;
        float ch = (a - b + c - d) * 0.5f;
        float cv = (a + b - c - d) * 0.5f;
        float cd = (a - b - c + d) * 0.5f;
        nxt[idx] = ca;
        Lb[0 * BS + i * P + j] = ch * s1;
        Lb[1 * BS + i * P + j] = cv * s2;
        Lb[2 * BS + i * P + j] = cd * s3;
        if (LV == 3) Lb[3 * BS + i * P + j] = ca * s0;
    }
}

template<int HH>
__device__ __forceinline__ void idwt_level(const float* __restrict__ cur,
                                           const float* __restrict__ Lb,
                                           float* __restrict__ outb, int tid)
{
    constexpr int P = HH + 1, BS = HH * P, H2 = 2 * HH;
    for (int idx = tid; idx < HH * HH; idx += 128) {
        int i = idx / HH, j = idx - i * HH;
        float ca = cur[idx];
        float ch = Lb[0 * BS + i * P + j];
        float cv = Lb[1 * BS + i * P + j];
        float cd = Lb[2 * BS + i * P + j];
        float a  = (ca + ch + cv + cd) * 0.5f;
        float b  = (ca - ch + cv - cd) * 0.5f;
        float c  = (ca + ch - cv - cd) * 0.5f;
        float d  = (ca - ch - cv + cd) * 0.5f;
        outb[(2 * i)     * H2 + 2 * j]     = a;
        outb[(2 * i)     * H2 + 2 * j + 1] = b;
        outb[(2 * i + 1) * H2 + 2 * j]     = c;
        outb[(2 * i + 1) * H2 + 2 * j + 1] = d;
    }
}

// ---------------------------------------------------------------------------
// Fat kernel
// ---------------------------------------------------------------------------
__global__ void __launch_bounds__(128, 2) fat_kernel(
    const float* __restrict__ X, const float* __restrict__ Wt,
    const float* __restrict__ bias, const float* __restrict__ sf,
    float* __restrict__ out)
{
    extern __shared__ float smem[];
    const int bid = blockIdx.x;
    const int tid = threadIdx.x;
    const int lane = tid & 31, warp = tid >> 5;

    // Placement-aware role split: bids {0..15} u {148..163} are wavelet CTAs
    const bool isWav = (bid < 16) || (bid >= 148 && bid < 164);

    if (isWav) {
        // ================= WAVELET branch: 4 images =================
        const int wavIdx = (bid < 16) ? bid : (16 + (bid - 148));   // 0..31

        float* A   = smem;          // 4096
        float* Wb0 = smem + 4096;   // 1024
        float* Wb1 = smem + 5120;   // 1024
        float* L0  = smem + 6144;   // 3*32*33 = 3168
        float* L1  = smem + 9312;   // 3*16*17 = 816
        float* L2  = smem + 10128;  // 3*8*9   = 216
        float* L3  = smem + 10344;  // 4*4*5   = 80

        for (int im = 0; im < 4; ++im) {
            const int b = wavIdx * 4 + im;
            const float4* xb = reinterpret_cast<const float4*>(X + (size_t)b * 4096);
            float4* Af = reinterpret_cast<float4*>(A);
            for (int i = tid; i < 1024; i += 128) Af[i] = xb[i];
            __syncthreads();

            dwt_level<0>(A,   Wb0, L0, sf, tid); __syncthreads();
            if (tid < 96) prune_row<32>(L0 + tid * 33);
            __syncthreads();
            dwt_level<1>(Wb0, Wb1, L1, sf, tid); __syncthreads();
            if (tid < 48) prune_row<16>(L1 + tid * 17);
            __syncthreads();
            dwt_level<2>(Wb1, Wb0, L2, sf, tid); __syncthreads();
            if (tid < 24) prune_row<8>(L2 + tid * 9);
            __syncthreads();
            dwt_level<3>(Wb0, Wb1, L3, sf, tid); __syncthreads();
            if (tid < 16) prune_row<4>(L3 + tid * 5);
            __syncthreads();

            if (tid < 16) {
                int i = tid >> 2, j = tid & 3;
                Wb0[tid] = L3[3 * 20 + i * 5 + j];
            }
            __syncthreads();
            idwt_level<4>(Wb0, L3, Wb1, tid);  __syncthreads();
            idwt_level<8>(Wb1, L2, Wb0, tid);  __syncthreads();
            idwt_level<16>(Wb0, L1, Wb1, tid); __syncthreads();
            idwt_level<32>(Wb1, L0, A, tid);   __syncthreads();

            // out[b,:] = wavelet + bias  (GEMM CTAs RED.ADD on top)
            const float4* Af4 = reinterpret_cast<const float4*>(A);
            const float4* Bv  = reinterpret_cast<const float4*>(bias);
            float4* O = reinterpret_cast<float4*>(out + (size_t)b * 4096);
            for (int i = tid; i < 1024; i += 128) {
                float4 wv = Af4[i], bb = Bv[i];
                float4 o;
                o.x = wv.x + bb.x; o.y = wv.y + bb.y;
                o.z = wv.z + bb.z; o.w = wv.w + bb.w;
                O[i] = o;
            }
            __syncthreads();
        }
        __threadfence();
        __syncthreads();
        if (tid == 0) atomicAdd(&g_wavdone, 1u);
        return;
    }

    // ================= GEMM branch (R15 geometry) =================
    // enumerate GEMM index g in 0..255 over non-wavelet bids
    const int g  = (bid < 148) ? (bid - 16) : (132 + (bid - 164));
    const int kz   = g & 1;                 // split-K rank
    const int tile = g >> 1;                // 0..127
    const int nb   = tile & 63, mb = tile >> 6;
    const int wm   = warp >> 1, wn = warp & 1;

    const float* Ag = X  + (size_t)mb * 64 * KDIM + (size_t)kz * KHALF;
    const float* Bg = Wt + (size_t)nb * 64 * KDIM + (size_t)kz * KHALF;

    const uint32_t sBase = (uint32_t)__cvta_generic_to_shared(smem);
    const uint32_t bOfs  = STAGES * 16384u;           // B region at 48 KB

    float acc[2][4][4];
#pragma unroll
    for (int a1 = 0; a1 < 2; ++a1)
#pragma unroll
        for (int a2 = 0; a2 < 4; ++a2)
#pragma unroll
            for (int a3 = 0; a3 < 4; ++a3) acc[a1][a2][a3] = 0.0f;

    const int j = lane >> 3, r = lane & 7;
    const int cja = (j >> 1);
    const int cjb = (j & 1);
    const uint32_t aRow0 = (uint32_t)((wm * 32 + (j & 1) * 8 + r) * 256);
    const uint32_t aRow1 = aRow0 + 16u * 256u;
    const uint32_t bRow0 = (uint32_t)((wn * 32 + (j >> 1) * 8 + r) * 256);
    const uint32_t bRow1 = bRow0 + 16u * 256u;

#define ISSUE(kt) {                                                            \
        int stg_ = (kt) % STAGES;                                              \
        uint32_t sa_ = sBase + (uint32_t)stg_ * 16384u;                        \
        uint32_t sb_ = sa_ + bOfs;                                             \
        const float* pa_ = Ag + (size_t)(kt) * BK;                             \
        const float* pb_ = Bg + (size_t)(kt) * BK;                             \
        _Pragma("unroll")                                                      \
        for (int i_ = 0; i_ < 8; ++i_) {                                       \
            int id_ = tid + 128 * i_;                                          \
            int row_ = id_ >> 4, c_ = id_ & 15;                                \
            uint32_t off_ = (uint32_t)(row_ * 256 + ((c_ ^ (row_ & 7)) << 4)); \
            cp_async16(sa_ + off_, pa_ + (size_t)row_ * KDIM + c_ * 4);        \
            cp_async16(sb_ + off_, pb_ + (size_t)row_ * KDIM + c_ * 4);        \
        } }

// fragment load for step s into parity buffer p
#define LOADFRAG(p, s) {                                                       \
        uint32_t ca = (uint32_t)((((2 * (s) + cja) ^ r)) << 4);                \
        uint32_t cb = (uint32_t)((((2 * (s) + cjb) ^ r)) << 4);                \
        ldsm_x4(av[p][0], aB + aRow0 + ca);                                    \
        ldsm_x4(av[p][1], aB + aRow1 + ca);                                    \
        ldsm_x4(bv[p][0], bB + bRow0 + cb);                                    \
        ldsm_x4(bv[p][1], bB + bRow1 + cb);                                    \
    }

// MMAs for parity buffer p (no cvt: raw fp32 -> HMMA.tf32, implicit RZ)
#define DOMMA(p) {                                                             \
        _Pragma("unroll")                                                      \
        for (int mt = 0; mt < 2; ++mt) {                                       \
            mma_tf32(acc[mt][0], av[p][mt], bv[p][0][0], bv[p][0][1]);         \
            mma_tf32(acc[mt][1], av[p][mt], bv[p][0][2], bv[p][0][3]);         \
            mma_tf32(acc[mt][2], av[p][mt], bv[p][1][0], bv[p][1][1]);         \
            mma_tf32(acc[mt][3], av[p][mt], bv[p][1][2], bv[p][1][3]);         \
        } }

// software-pipelined compute: prefetch step s+1's fragments before step s's MMAs
#define COMPUTE(stg) {                                                         \
        uint32_t aB = sBase + (uint32_t)(stg) * 16384u;                        \
        uint32_t bB = aB + bOfs;                                               \
        uint32_t av[2][2][4], bv[2][2][4];                                     \
        LOADFRAG(0, 0)                                                         \
        _Pragma("unroll")                                                      \
        for (int s = 0; s < 8; ++s) {                                          \
            int cur_ = s & 1, nxt_ = cur_ ^ 1;                                 \
            if (s < 7) LOADFRAG(nxt_, s + 1)                                   \
            DOMMA(cur_)                                                        \
        } }

    ISSUE(0); asm volatile("cp.async.commit_group;");
    ISSUE(1); asm volatile("cp.async.commit_group;");

    for (int kt = 0; kt < NT2; ++kt) {
        asm volatile("cp.async.wait_group 1;");
        __syncthreads();
        COMPUTE(kt % STAGES);
        if (kt + 2 < NT2) { ISSUE(kt + 2); }
        asm volatile("cp.async.commit_group;");
    }

    // ---- wait for wavelet CTAs (they wrote out = wav + bias) ----
    if (tid == 0) {
        unsigned v;
        do {
            asm volatile("ld.acquire.gpu.global.u32 %0, [%1];"
                         : "=r"(v) : "l"(&g_wavdone));
        } while (v < WAV_CTAS);
        unsigned old = atomicAdd(&g_gate, 1u);
        if (old == GEMM_CTAS - 1) {           // last GEMM CTA resets counters
            atomicExch(&g_wavdone, 0u);
            atomicExch(&g_gate, 0u);
        }
    }
    __syncthreads();

    // ---- accumulate into out via RED.ADD.v2 ----
    const int rbase = mb * 64 + wm * 32 + (lane >> 2);
    const int cbase = nb * 64 + wn * 32 + (lane & 3) * 2;
#pragma unroll
    for (int mt = 0; mt < 2; ++mt) {
#pragma unroll
        for (int nt = 0; nt < 4; ++nt) {
            int gn  = cbase + nt * 8;
            int gm0 = rbase + mt * 16;
            red_add_v2(out + (size_t)gm0 * 4096 + gn,
                       acc[mt][nt][0], acc[mt][nt][1]);
            red_add_v2(out + (size_t)(gm0 + 8) * 4096 + gn,
                       acc[mt][nt][2], acc[mt][nt][3]);
        }
    }
#undef ISSUE
#undef LOADFRAG
#undef DOMMA
#undef COMPUTE
}

// ---------------------------------------------------------------------------
// Launch
// ---------------------------------------------------------------------------
extern "C" void kernel_launch(void* const* d_in, const int* in_sizes, int n_in,
                              void* d_out, int out_size)
{
    const float* x    = (const float*)d_in[0];   // [128, 4096]
    const float* Wt   = (const float*)d_in[1];   // [4096, 4096]
    const float* bias = (const float*)d_in[2];   // [4096]
    const float* sf   = (const float*)d_in[3];   // [4, 4]
    float* out = (float*)d_out;                  // [128, 4096]

    (void)in_sizes; (void)n_in; (void)out_size;

    const int smemBytes = STAGES * 16384 * 2;    // 96 KB -> 2 CTAs/SM
    cudaFuncSetAttribute(fat_kernel,
                         cudaFuncAttributeMaxDynamicSharedMemorySize, smemBytes);

    fat_kernel<<<288, 128, smemBytes>>>(x, Wt, bias, sf, out);
}